// round 1
// baseline (speedup 1.0000x reference)
#include <cuda_runtime.h>
#include <math.h>

#define B_ 2
#define S_ 2048
#define D_ 4096
#define H_ 32
#define KV_ 8
#define HD_ 128
#define T_ (B_*S_)
#define REP_ (H_/KV_)

// Scratch (device globals: allocation-free rule)
__device__ float g_q[T_ * D_];            // 134 MB
__device__ float g_k[T_ * KV_ * HD_];     // 33.5 MB
__device__ float g_v[T_ * KV_ * HD_];     // 33.5 MB
__device__ float g_attn[T_ * D_];         // 134 MB

// ---------------------------------------------------------------------------
// SGEMM: C[M,N] = A[M,K] @ W[N,K]^T   (both operands K-major, "NT")
// 128x128 block tile, BK=16, 8x8 per-thread tile, 256 threads.
// ---------------------------------------------------------------------------
__global__ void __launch_bounds__(256, 2)
sgemm_nt(const float* __restrict__ A, const float* __restrict__ Wt,
         float* __restrict__ C, int M, int N, int K)
{
    __shared__ __align__(16) float As[16][132];
    __shared__ __align__(16) float Bs[16][132];

    const int tid = threadIdx.x;
    const int tx = tid & 15;
    const int ty = tid >> 4;
    const int bm = blockIdx.y * 128;
    const int bn = blockIdx.x * 128;

    const float* Ab = A  + (size_t)bm * K;
    const float* Bb = Wt + (size_t)bn * K;

    float acc[8][8];
    #pragma unroll
    for (int i = 0; i < 8; i++)
        #pragma unroll
        for (int j = 0; j < 8; j++) acc[i][j] = 0.f;

    const int lrow = tid >> 2;          // 0..63
    const int lcol = (tid & 3) << 2;    // 0,4,8,12

    for (int k0 = 0; k0 < K; k0 += 16) {
        #pragma unroll
        for (int r = 0; r < 2; r++) {
            int row = lrow + r * 64;
            float4 a = *(const float4*)(Ab + (size_t)row * K + k0 + lcol);
            As[lcol+0][row] = a.x; As[lcol+1][row] = a.y;
            As[lcol+2][row] = a.z; As[lcol+3][row] = a.w;
            float4 b = *(const float4*)(Bb + (size_t)row * K + k0 + lcol);
            Bs[lcol+0][row] = b.x; Bs[lcol+1][row] = b.y;
            Bs[lcol+2][row] = b.z; Bs[lcol+3][row] = b.w;
        }
        __syncthreads();

        #pragma unroll
        for (int kk = 0; kk < 16; kk++) {
            float ra[8], rb[8];
            *(float4*)&ra[0] = *(const float4*)&As[kk][ty*8];
            *(float4*)&ra[4] = *(const float4*)&As[kk][ty*8+4];
            *(float4*)&rb[0] = *(const float4*)&Bs[kk][tx*8];
            *(float4*)&rb[4] = *(const float4*)&Bs[kk][tx*8+4];
            #pragma unroll
            for (int i = 0; i < 8; i++)
                #pragma unroll
                for (int j = 0; j < 8; j++)
                    acc[i][j] += ra[i] * rb[j];
        }
        __syncthreads();
    }

    #pragma unroll
    for (int i = 0; i < 8; i++) {
        int row = bm + ty * 8 + i;
        float* cp = C + (size_t)row * N + bn + tx * 8;
        *(float4*)cp     = make_float4(acc[i][0], acc[i][1], acc[i][2], acc[i][3]);
        *(float4*)(cp+4) = make_float4(acc[i][4], acc[i][5], acc[i][6], acc[i][7]);
    }
}

// ---------------------------------------------------------------------------
// RoPE (interleaved pairs): one thread per (token, head, pair)
// ---------------------------------------------------------------------------
__global__ void rope_kernel(float* __restrict__ qk, const float* __restrict__ fc,
                            const float* __restrict__ fs, int heads)
{
    int idx = blockIdx.x * blockDim.x + threadIdx.x;
    int total = T_ * heads * (HD_/2);
    if (idx >= total) return;
    int i   = idx & 63;
    int rem = idx >> 6;
    int h   = rem % heads;
    int t   = rem / heads;
    int s   = t & (S_ - 1);
    float c  = fc[s*64 + i];
    float sn = fs[s*64 + i];
    size_t base = (size_t)t * heads * HD_ + h * HD_ + 2*i;
    float x0 = qk[base], x1 = qk[base+1];
    qk[base]   = x0 * c  - x1 * sn;
    qk[base+1] = x0 * sn + x1 * c;
}

// ---------------------------------------------------------------------------
// Flash attention, fp32, causal, GQA (4 q-heads per kv-head)
// Block = (qtile 64, head, batch), 256 threads (16x16), online softmax.
// Q/K stored d-major in smem ([d][row], pad 68) so the 4x4 score tile reads
// conflict-free float4s; V row-major (pad 132); P staged in smem for PV.
// ---------------------------------------------------------------------------
#define FA_SMEM_FLOATS (128*68 + 128*68 + 64*132 + 64*65 + 64*17 + 3*64)
#define FA_SMEM_BYTES  (FA_SMEM_FLOATS * 4)

__global__ void __launch_bounds__(256, 1)
flash_kernel(const float* __restrict__ Qg, const float* __restrict__ Kg,
             const float* __restrict__ Vg, float* __restrict__ Og)
{
    extern __shared__ __align__(16) float sm[];
    float* Qts  = sm;                 // [128][68]  (d-major)
    float* Kts  = Qts + 128*68;       // [128][68]  (d-major)
    float* Vs   = Kts + 128*68;       // [64][132]  (row-major)
    float* Ps   = Vs  + 64*132;       // [64][65]
    float* red  = Ps  + 64*65;        // [64][17]
    float* m_sm = red + 64*17;        // [64]
    float* l_sm = m_sm + 64;          // [64]
    float* al_sm= l_sm + 64;          // [64]

    const int tid = threadIdx.x;
    const int tx  = tid & 15;
    const int ty  = tid >> 4;
    const int qt  = blockIdx.x;
    const int h   = blockIdx.y;
    const int b   = blockIdx.z;
    const int g   = h / REP_;
    const int q0  = qt * 64;
    const int t0  = b * S_ + q0;
    const float scale = 0.08838834764831845f;  // 1/sqrt(128)

    // Load Q tile transposed+scaled. warp: 32 rows, fixed c4 -> conflict-free stores
    #pragma unroll
    for (int r = 0; r < 8; r++) {
        int idx = tid + r * 256;
        int row = idx & 63;
        int c4  = idx >> 6;
        float4 v = *(const float4*)(Qg + (size_t)(t0 + row) * D_ + h * HD_ + c4 * 4);
        Qts[(c4*4+0)*68 + row] = v.x * scale;
        Qts[(c4*4+1)*68 + row] = v.y * scale;
        Qts[(c4*4+2)*68 + row] = v.z * scale;
        Qts[(c4*4+3)*68 + row] = v.w * scale;
    }
    if (tid < 64) { m_sm[tid] = -1e30f; l_sm[tid] = 0.f; }

    float oacc[4][8];
    #pragma unroll
    for (int i = 0; i < 4; i++)
        #pragma unroll
        for (int j = 0; j < 8; j++) oacc[i][j] = 0.f;

    const int ry  = ty << 2;   // row base (score + PV rows)
    const int cx4 = tx << 2;   // score col base
    const int cx8 = tx << 3;   // PV col base

    for (int kt = 0; kt <= qt; kt++) {
        const int k0  = kt * 64;
        const int tk0 = b * S_ + k0;

        // K tile transposed
        #pragma unroll
        for (int r = 0; r < 8; r++) {
            int idx = tid + r * 256;
            int row = idx & 63;
            int c4  = idx >> 6;
            float4 v = *(const float4*)(Kg + (size_t)(tk0 + row) * (KV_*HD_) + g * HD_ + c4 * 4);
            Kts[(c4*4+0)*68 + row] = v.x;
            Kts[(c4*4+1)*68 + row] = v.y;
            Kts[(c4*4+2)*68 + row] = v.z;
            Kts[(c4*4+3)*68 + row] = v.w;
        }
        // V tile row-major (coalesced)
        #pragma unroll
        for (int r = 0; r < 8; r++) {
            int idx = tid + r * 256;
            int row = idx >> 5;
            int c4  = idx & 31;
            float4 v = *(const float4*)(Vg + (size_t)(tk0 + row) * (KV_*HD_) + g * HD_ + c4 * 4);
            *(float4*)&Vs[row*132 + c4*4] = v;
        }
        __syncthreads();   // S1: tiles ready

        // scores: 4x4 per thread over d=0..127
        float sacc[4][4];
        #pragma unroll
        for (int i = 0; i < 4; i++)
            #pragma unroll
            for (int j = 0; j < 4; j++) sacc[i][j] = 0.f;

        #pragma unroll 8
        for (int d = 0; d < 128; d++) {
            float4 qa = *(const float4*)&Qts[d*68 + ry];
            float4 kb = *(const float4*)&Kts[d*68 + cx4];
            float qv[4] = {qa.x, qa.y, qa.z, qa.w};
            float kv[4] = {kb.x, kb.y, kb.z, kb.w};
            #pragma unroll
            for (int i = 0; i < 4; i++)
                #pragma unroll
                for (int j = 0; j < 4; j++)
                    sacc[i][j] += qv[i] * kv[j];
        }

        if (kt == qt) {   // diagonal tile: causal mask (local indices, k0 == q0)
            #pragma unroll
            for (int i = 0; i < 4; i++)
                #pragma unroll
                for (int j = 0; j < 4; j++)
                    if (cx4 + j > ry + i) sacc[i][j] = -1e30f;
        }

        // local row max -> reduction buffer
        #pragma unroll
        for (int i = 0; i < 4; i++) {
            float m = fmaxf(fmaxf(sacc[i][0], sacc[i][1]), fmaxf(sacc[i][2], sacc[i][3]));
            red[(ry+i)*17 + tx] = m;
        }
        __syncthreads();   // S2
        if (tid < 64) {
            float m = red[tid*17];
            #pragma unroll
            for (int t = 1; t < 16; t++) m = fmaxf(m, red[tid*17 + t]);
            float mp = m_sm[tid];
            float mn = fmaxf(mp, m);
            float a  = __expf(mp - mn);
            m_sm[tid]  = mn;
            al_sm[tid] = a;
            l_sm[tid] *= a;
        }
        __syncthreads();   // S3

        // P = exp(s - m), stage to smem; local row sums; rescale O accumulators
        #pragma unroll
        for (int i = 0; i < 4; i++) {
            float mn = m_sm[ry+i];
            float s = 0.f;
            #pragma unroll
            for (int j = 0; j < 4; j++) {
                float p = __expf(sacc[i][j] - mn);
                Ps[(ry+i)*65 + cx4 + j] = p;
                s += p;
            }
            red[(ry+i)*17 + tx] = s;
            float a = al_sm[ry+i];
            #pragma unroll
            for (int c = 0; c < 8; c++) oacc[i][c] *= a;
        }
        __syncthreads();   // S4: Ps + row sums ready
        if (tid < 64) {
            float s = 0.f;
            #pragma unroll
            for (int t = 0; t < 16; t++) s += red[tid*17 + t];
            l_sm[tid] += s;
        }

        // O += P @ V  (4 rows x 8 cols per thread)
        #pragma unroll 4
        for (int j = 0; j < 64; j++) {
            float pp[4];
            pp[0] = Ps[(ry+0)*65 + j];
            pp[1] = Ps[(ry+1)*65 + j];
            pp[2] = Ps[(ry+2)*65 + j];
            pp[3] = Ps[(ry+3)*65 + j];
            float4 v0 = *(const float4*)&Vs[j*132 + cx8];
            float4 v1 = *(const float4*)&Vs[j*132 + cx8 + 4];
            float vv[8] = {v0.x, v0.y, v0.z, v0.w, v1.x, v1.y, v1.z, v1.w};
            #pragma unroll
            for (int i = 0; i < 4; i++)
                #pragma unroll
                for (int c = 0; c < 8; c++)
                    oacc[i][c] += pp[i] * vv[c];
        }
        __syncthreads();   // S5: PV done before tiles are overwritten
    }

    #pragma unroll
    for (int i = 0; i < 4; i++) {
        int row = ry + i;
        float inv = 1.0f / l_sm[row];
        float* op = Og + (size_t)(t0 + row) * D_ + h * HD_ + cx8;
        *(float4*)op     = make_float4(oacc[i][0]*inv, oacc[i][1]*inv,
                                       oacc[i][2]*inv, oacc[i][3]*inv);
        *(float4*)(op+4) = make_float4(oacc[i][4]*inv, oacc[i][5]*inv,
                                       oacc[i][6]*inv, oacc[i][7]*inv);
    }
}

// ---------------------------------------------------------------------------
extern "C" void kernel_launch(void* const* d_in, const int* in_sizes, int n_in,
                              void* d_out, int out_size)
{
    const float* x  = (const float*)d_in[0];
    const float* fc = (const float*)d_in[1];
    const float* fs = (const float*)d_in[2];
    const float* wq = (const float*)d_in[3];
    const float* wk = (const float*)d_in[4];
    const float* wv = (const float*)d_in[5];
    const float* wo = (const float*)d_in[6];
    float* out = (float*)d_out;

    float *qp, *kp, *vp, *ap;
    cudaGetSymbolAddress((void**)&qp, g_q);
    cudaGetSymbolAddress((void**)&kp, g_k);
    cudaGetSymbolAddress((void**)&vp, g_v);
    cudaGetSymbolAddress((void**)&ap, g_attn);

    cudaFuncSetAttribute(flash_kernel,
                         cudaFuncAttributeMaxDynamicSharedMemorySize, FA_SMEM_BYTES);

    dim3 blk(256);
    // QKV projections
    sgemm_nt<<<dim3(D_/128,        T_/128), blk>>>(x, wq, qp, T_, D_,      D_);
    sgemm_nt<<<dim3((KV_*HD_)/128, T_/128), blk>>>(x, wk, kp, T_, KV_*HD_, D_);
    sgemm_nt<<<dim3((KV_*HD_)/128, T_/128), blk>>>(x, wv, vp, T_, KV_*HD_, D_);
    // RoPE on q, k
    rope_kernel<<<(T_*H_*(HD_/2))/256,  256>>>(qp, fc, fs, H_);
    rope_kernel<<<(T_*KV_*(HD_/2))/256, 256>>>(kp, fc, fs, KV_);
    // causal GQA flash attention
    flash_kernel<<<dim3(S_/64, H_, B_), blk, FA_SMEM_BYTES>>>(qp, kp, vp, ap);
    // output projection
    sgemm_nt<<<dim3(D_/128, T_/128), blk>>>(ap, wo, out, T_, D_, D_);
}

// round 3
// speedup vs baseline: 2.0037x; 2.0037x over previous
#include <cuda_runtime.h>
#include <cuda_bf16.h>
#include <math.h>
#include <cstdint>

#define B_ 2
#define S_ 2048
#define D_ 4096
#define H_ 32
#define KV_ 8
#define HD_ 128
#define T_ (B_*S_)
#define REP_ (H_/KV_)

// ---------------------------------------------------------------------------
// Scratch (device globals: allocation-free rule)
// ---------------------------------------------------------------------------
__device__ float g_q[T_ * D_];
__device__ float g_k[T_ * KV_ * HD_];
__device__ float g_v[T_ * KV_ * HD_];
__device__ float g_attn[T_ * D_];

__device__ __nv_bfloat16 g_xh[T_ * D_];
__device__ __nv_bfloat16 g_xl[T_ * D_];
__device__ __nv_bfloat16 g_ah[T_ * D_];
__device__ __nv_bfloat16 g_al[T_ * D_];
__device__ __nv_bfloat16 g_wqh[D_ * D_];
__device__ __nv_bfloat16 g_wql[D_ * D_];
__device__ __nv_bfloat16 g_wkh[KV_ * HD_ * D_];
__device__ __nv_bfloat16 g_wkl[KV_ * HD_ * D_];
__device__ __nv_bfloat16 g_wvh[KV_ * HD_ * D_];
__device__ __nv_bfloat16 g_wvl[KV_ * HD_ * D_];
__device__ __nv_bfloat16 g_woh[D_ * D_];
__device__ __nv_bfloat16 g_wol[D_ * D_];

// ---------------------------------------------------------------------------
// Helpers
// ---------------------------------------------------------------------------
__device__ __forceinline__ uint32_t smem_to_u32(const void* smem_ptr) {
    uint32_t addr;
    asm("{ .reg .u64 tmp; cvta.to.shared.u64 tmp, %1; cvt.u32.u64 %0, tmp; }"
        : "=r"(addr) : "l"(smem_ptr));
    return addr;
}
__device__ __forceinline__ void cp_async16(uint32_t saddr, const void* gaddr) {
    asm volatile("cp.async.cg.shared.global [%0], [%1], 16;"
                 :: "r"(saddr), "l"(gaddr));
}
#define CP_COMMIT() asm volatile("cp.async.commit_group;")
#define CP_WAIT(n)  asm volatile("cp.async.wait_group %0;" :: "n"(n))

__device__ __forceinline__ uint32_t lds32(uint32_t addr) {
    uint32_t v;
    asm("ld.shared.b32 %0, [%1];" : "=r"(v) : "r"(addr));
    return v;
}

#define MMA_BF16(d, a, b) \
    asm volatile("mma.sync.aligned.m16n8k16.row.col.f32.bf16.bf16.f32 " \
        "{%0,%1,%2,%3}, {%4,%5,%6,%7}, {%8,%9}, {%0,%1,%2,%3};" \
        : "+f"((d)[0]), "+f"((d)[1]), "+f"((d)[2]), "+f"((d)[3]) \
        : "r"((a)[0]), "r"((a)[1]), "r"((a)[2]), "r"((a)[3]), \
          "r"((b)[0]), "r"((b)[1]))

// ---------------------------------------------------------------------------
// fp32 -> bf16 hi/lo split
// ---------------------------------------------------------------------------
__global__ void split_bf16(const float* __restrict__ X,
                           __nv_bfloat16* __restrict__ Hh,
                           __nv_bfloat16* __restrict__ Ll, int n4)
{
    int i = blockIdx.x * blockDim.x + threadIdx.x;
    if (i >= n4) return;
    float4 v = reinterpret_cast<const float4*>(X)[i];
    __nv_bfloat16 h0 = __float2bfloat16(v.x);
    __nv_bfloat16 h1 = __float2bfloat16(v.y);
    __nv_bfloat16 h2 = __float2bfloat16(v.z);
    __nv_bfloat16 h3 = __float2bfloat16(v.w);
    __nv_bfloat16 l0 = __float2bfloat16(v.x - __bfloat162float(h0));
    __nv_bfloat16 l1 = __float2bfloat16(v.y - __bfloat162float(h1));
    __nv_bfloat16 l2 = __float2bfloat16(v.z - __bfloat162float(h2));
    __nv_bfloat16 l3 = __float2bfloat16(v.w - __bfloat162float(h3));
    ushort4 hp, lp;
    hp.x = __bfloat16_as_ushort(h0); hp.y = __bfloat16_as_ushort(h1);
    hp.z = __bfloat16_as_ushort(h2); hp.w = __bfloat16_as_ushort(h3);
    lp.x = __bfloat16_as_ushort(l0); lp.y = __bfloat16_as_ushort(l1);
    lp.z = __bfloat16_as_ushort(l2); lp.w = __bfloat16_as_ushort(l3);
    reinterpret_cast<ushort4*>(Hh)[i] = hp;
    reinterpret_cast<ushort4*>(Ll)[i] = lp;
}

// ---------------------------------------------------------------------------
// bf16x3 GEMM via mma.sync: C[M,N] = A[M,K] @ W[N,K]^T, fp32 accumulate.
// CTA 128x128, BK=64, 8 warps (2x4), warp tile 64x32, cp.async double-buffer.
// Smem tiles: 128 rows x 64 bf16 (128B rows), XOR swizzle: chunk ^= row%8.
// ---------------------------------------------------------------------------
#define GT_BYTES 16384                 // one tile: 128 * 128B
#define GSTAGE_BYTES (4 * GT_BYTES)    // Ah, Al, Bh, Bl
#define GEMM_SMEM_BYTES (2 * GSTAGE_BYTES)

__device__ __forceinline__ void gemm_stage_copy(
    uint32_t sbase, const __nv_bfloat16* a_h, const __nv_bfloat16* a_l,
    const __nv_bfloat16* b_h, const __nv_bfloat16* b_l,
    int K, int k0, int tid)
{
    const __nv_bfloat16* srcs[4] = {a_h, a_l, b_h, b_l};
    #pragma unroll
    for (int t = 0; t < 4; t++) {
        const __nv_bfloat16* src = srcs[t];
        #pragma unroll
        for (int p = 0; p < 4; p++) {
            int idx = p * 256 + tid;
            int row = idx >> 3;
            int ch  = idx & 7;
            const char* gp = (const char*)(src + (size_t)row * K + k0) + ch * 16;
            uint32_t soff = (uint32_t)(t * GT_BYTES + row * 128 +
                                       ((ch * 16) ^ ((row & 7) << 4)));
            cp_async16(sbase + soff, gp);
        }
    }
}

__global__ void __launch_bounds__(256, 1)
gemm_bf16x3(const __nv_bfloat16* __restrict__ Ah, const __nv_bfloat16* __restrict__ Al,
            const __nv_bfloat16* __restrict__ Bh, const __nv_bfloat16* __restrict__ Bl,
            float* __restrict__ C, int M, int N, int K)
{
    extern __shared__ __align__(1024) char smem[];
    const uint32_t sb0 = smem_to_u32(smem);
    const int tid  = threadIdx.x;
    const int wid  = tid >> 5;
    const int lane = tid & 31;
    const int bm = blockIdx.y * 128;
    const int bn = blockIdx.x * 128;
    const int warp_m = (wid >> 2) * 64;
    const int warp_n = (wid & 3) * 32;
    const int NC = K >> 6;

    const __nv_bfloat16* a_h = Ah + (size_t)bm * K;
    const __nv_bfloat16* a_l = Al + (size_t)bm * K;
    const __nv_bfloat16* b_h = Bh + (size_t)bn * K;
    const __nv_bfloat16* b_l = Bl + (size_t)bn * K;

    float acc[4][4][4];
    #pragma unroll
    for (int i = 0; i < 4; i++)
        #pragma unroll
        for (int j = 0; j < 4; j++)
            #pragma unroll
            for (int r = 0; r < 4; r++) acc[i][j][r] = 0.f;

    // lane decomposition for fragments
    const int lg  = lane >> 2;        // 0..7 (row-in-8 group)
    const int lk4 = (lane & 3) * 4;   // k byte offset within 32B group

    gemm_stage_copy(sb0, a_h, a_l, b_h, b_l, K, 0, tid);
    CP_COMMIT();

    for (int c = 0; c < NC; c++) {
        if (c + 1 < NC) {
            gemm_stage_copy(sb0 + ((c + 1) & 1) * GSTAGE_BYTES,
                            a_h, a_l, b_h, b_l, K, (c + 1) << 6, tid);
            CP_COMMIT();
            CP_WAIT(1);
        } else {
            CP_WAIT(0);
        }
        __syncthreads();

        const uint32_t sb = sb0 + (c & 1) * GSTAGE_BYTES;

        #pragma unroll
        for (int ks = 0; ks < 4; ks++) {
            const int kb = ks * 32 + lk4;    // byte offset of this lane's k pair

            uint32_t ah[4][4], al[4][4], bh[4][2], bl[4][2];
            #pragma unroll
            for (int mt = 0; mt < 4; mt++) {
                int r0 = warp_m + mt * 16 + lg;
                int r1 = r0 + 8;
                uint32_t rb0 = r0 * 128, rx0 = (r0 & 7) << 4;
                uint32_t rb1 = r1 * 128, rx1 = (r1 & 7) << 4;
                ah[mt][0] = lds32(sb + rb0 + (kb ^ rx0));
                ah[mt][1] = lds32(sb + rb1 + (kb ^ rx1));
                ah[mt][2] = lds32(sb + rb0 + ((kb + 16) ^ rx0));
                ah[mt][3] = lds32(sb + rb1 + ((kb + 16) ^ rx1));
                al[mt][0] = lds32(sb + GT_BYTES + rb0 + (kb ^ rx0));
                al[mt][1] = lds32(sb + GT_BYTES + rb1 + (kb ^ rx1));
                al[mt][2] = lds32(sb + GT_BYTES + rb0 + ((kb + 16) ^ rx0));
                al[mt][3] = lds32(sb + GT_BYTES + rb1 + ((kb + 16) ^ rx1));
            }
            #pragma unroll
            for (int nt = 0; nt < 4; nt++) {
                int n = warp_n + nt * 8 + lg;
                uint32_t rb = n * 128, rx = (n & 7) << 4;
                bh[nt][0] = lds32(sb + 2*GT_BYTES + rb + (kb ^ rx));
                bh[nt][1] = lds32(sb + 2*GT_BYTES + rb + ((kb + 16) ^ rx));
                bl[nt][0] = lds32(sb + 3*GT_BYTES + rb + (kb ^ rx));
                bl[nt][1] = lds32(sb + 3*GT_BYTES + rb + ((kb + 16) ^ rx));
            }
            #pragma unroll
            for (int mt = 0; mt < 4; mt++)
                #pragma unroll
                for (int nt = 0; nt < 4; nt++) {
                    MMA_BF16(acc[mt][nt], ah[mt], bh[nt]);
                    MMA_BF16(acc[mt][nt], al[mt], bh[nt]);
                    MMA_BF16(acc[mt][nt], ah[mt], bl[nt]);
                }
        }
        __syncthreads();
    }

    // epilogue: c0,c1 -> (row, col..col+1); c2,c3 -> (row+8, col..col+1)
    #pragma unroll
    for (int mt = 0; mt < 4; mt++) {
        int row = bm + warp_m + mt * 16 + lg;
        #pragma unroll
        for (int nt = 0; nt < 4; nt++) {
            int col = bn + warp_n + nt * 8 + (lane & 3) * 2;
            *(float2*)(C + (size_t)row * N + col) =
                make_float2(acc[mt][nt][0], acc[mt][nt][1]);
            *(float2*)(C + (size_t)(row + 8) * N + col) =
                make_float2(acc[mt][nt][2], acc[mt][nt][3]);
        }
    }
}

// ---------------------------------------------------------------------------
// RoPE (interleaved pairs)
// ---------------------------------------------------------------------------
__global__ void rope_kernel(float* __restrict__ qk, const float* __restrict__ fc,
                            const float* __restrict__ fs, int heads)
{
    int idx = blockIdx.x * blockDim.x + threadIdx.x;
    int total = T_ * heads * (HD_/2);
    if (idx >= total) return;
    int i   = idx & 63;
    int rem = idx >> 6;
    int h   = rem % heads;
    int t   = rem / heads;
    int s   = t & (S_ - 1);
    float c  = fc[s*64 + i];
    float sn = fs[s*64 + i];
    size_t base = (size_t)t * heads * HD_ + h * HD_ + 2*i;
    float x0 = qk[base], x1 = qk[base+1];
    qk[base]   = x0 * c  - x1 * sn;
    qk[base+1] = x0 * sn + x1 * c;
}

// ---------------------------------------------------------------------------
// Flash attention, fp32, causal, GQA (unchanged — known correct)
// ---------------------------------------------------------------------------
#define FA_SMEM_FLOATS (128*68 + 128*68 + 64*132 + 64*65 + 64*17 + 3*64)
#define FA_SMEM_BYTES  (FA_SMEM_FLOATS * 4)

__global__ void __launch_bounds__(256, 1)
flash_kernel(const float* __restrict__ Qg, const float* __restrict__ Kg,
             const float* __restrict__ Vg, float* __restrict__ Og)
{
    extern __shared__ __align__(16) float sm[];
    float* Qts  = sm;
    float* Kts  = Qts + 128*68;
    float* Vs   = Kts + 128*68;
    float* Ps   = Vs  + 64*132;
    float* red  = Ps  + 64*65;
    float* m_sm = red + 64*17;
    float* l_sm = m_sm + 64;
    float* al_sm= l_sm + 64;

    const int tid = threadIdx.x;
    const int tx  = tid & 15;
    const int ty  = tid >> 4;
    const int qt  = blockIdx.x;
    const int h   = blockIdx.y;
    const int b   = blockIdx.z;
    const int g   = h / REP_;
    const int q0  = qt * 64;
    const int t0  = b * S_ + q0;
    const float scale = 0.08838834764831845f;

    #pragma unroll
    for (int r = 0; r < 8; r++) {
        int idx = tid + r * 256;
        int row = idx & 63;
        int c4  = idx >> 6;
        float4 v = *(const float4*)(Qg + (size_t)(t0 + row) * D_ + h * HD_ + c4 * 4);
        Qts[(c4*4+0)*68 + row] = v.x * scale;
        Qts[(c4*4+1)*68 + row] = v.y * scale;
        Qts[(c4*4+2)*68 + row] = v.z * scale;
        Qts[(c4*4+3)*68 + row] = v.w * scale;
    }
    if (tid < 64) { m_sm[tid] = -1e30f; l_sm[tid] = 0.f; }

    float oacc[4][8];
    #pragma unroll
    for (int i = 0; i < 4; i++)
        #pragma unroll
        for (int j = 0; j < 8; j++) oacc[i][j] = 0.f;

    const int ry  = ty << 2;
    const int cx4 = tx << 2;
    const int cx8 = tx << 3;

    for (int kt = 0; kt <= qt; kt++) {
        const int tk0 = b * S_ + kt * 64;

        #pragma unroll
        for (int r = 0; r < 8; r++) {
            int idx = tid + r * 256;
            int row = idx & 63;
            int c4  = idx >> 6;
            float4 v = *(const float4*)(Kg + (size_t)(tk0 + row) * (KV_*HD_) + g * HD_ + c4 * 4);
            Kts[(c4*4+0)*68 + row] = v.x;
            Kts[(c4*4+1)*68 + row] = v.y;
            Kts[(c4*4+2)*68 + row] = v.z;
            Kts[(c4*4+3)*68 + row] = v.w;
        }
        #pragma unroll
        for (int r = 0; r < 8; r++) {
            int idx = tid + r * 256;
            int row = idx >> 5;
            int c4  = idx & 31;
            float4 v = *(const float4*)(Vg + (size_t)(tk0 + row) * (KV_*HD_) + g * HD_ + c4 * 4);
            *(float4*)&Vs[row*132 + c4*4] = v;
        }
        __syncthreads();

        float sacc[4][4];
        #pragma unroll
        for (int i = 0; i < 4; i++)
            #pragma unroll
            for (int j = 0; j < 4; j++) sacc[i][j] = 0.f;

        #pragma unroll 8
        for (int d = 0; d < 128; d++) {
            float4 qa = *(const float4*)&Qts[d*68 + ry];
            float4 kb = *(const float4*)&Kts[d*68 + cx4];
            float qv[4] = {qa.x, qa.y, qa.z, qa.w};
            float kv[4] = {kb.x, kb.y, kb.z, kb.w};
            #pragma unroll
            for (int i = 0; i < 4; i++)
                #pragma unroll
                for (int j = 0; j < 4; j++)
                    sacc[i][j] += qv[i] * kv[j];
        }

        if (kt == qt) {
            #pragma unroll
            for (int i = 0; i < 4; i++)
                #pragma unroll
                for (int j = 0; j < 4; j++)
                    if (cx4 + j > ry + i) sacc[i][j] = -1e30f;
        }

        #pragma unroll
        for (int i = 0; i < 4; i++) {
            float m = fmaxf(fmaxf(sacc[i][0], sacc[i][1]), fmaxf(sacc[i][2], sacc[i][3]));
            red[(ry+i)*17 + tx] = m;
        }
        __syncthreads();
        if (tid < 64) {
            float m = red[tid*17];
            #pragma unroll
            for (int t = 1; t < 16; t++) m = fmaxf(m, red[tid*17 + t]);
            float mp = m_sm[tid];
            float mn = fmaxf(mp, m);
            float a  = __expf(mp - mn);
            m_sm[tid]  = mn;
            al_sm[tid] = a;
            l_sm[tid] *= a;
        }
        __syncthreads();

        #pragma unroll
        for (int i = 0; i < 4; i++) {
            float mn = m_sm[ry+i];
            float s = 0.f;
            #pragma unroll
            for (int j = 0; j < 4; j++) {
                float p = __expf(sacc[i][j] - mn);
                Ps[(ry+i)*65 + cx4 + j] = p;
                s += p;
            }
            red[(ry+i)*17 + tx] = s;
            float a = al_sm[ry+i];
            #pragma unroll
            for (int c = 0; c < 8; c++) oacc[i][c] *= a;
        }
        __syncthreads();
        if (tid < 64) {
            float s = 0.f;
            #pragma unroll
            for (int t = 0; t < 16; t++) s += red[tid*17 + t];
            l_sm[tid] += s;
        }

        #pragma unroll 4
        for (int j = 0; j < 64; j++) {
            float pp[4];
            pp[0] = Ps[(ry+0)*65 + j];
            pp[1] = Ps[(ry+1)*65 + j];
            pp[2] = Ps[(ry+2)*65 + j];
            pp[3] = Ps[(ry+3)*65 + j];
            float4 v0 = *(const float4*)&Vs[j*132 + cx8];
            float4 v1 = *(const float4*)&Vs[j*132 + cx8 + 4];
            float vv[8] = {v0.x, v0.y, v0.z, v0.w, v1.x, v1.y, v1.z, v1.w};
            #pragma unroll
            for (int i = 0; i < 4; i++)
                #pragma unroll
                for (int c = 0; c < 8; c++)
                    oacc[i][c] += pp[i] * vv[c];
        }
        __syncthreads();
    }

    #pragma unroll
    for (int i = 0; i < 4; i++) {
        int row = ry + i;
        float inv = 1.0f / l_sm[row];
        float* op = Og + (size_t)(t0 + row) * D_ + h * HD_ + cx8;
        *(float4*)op     = make_float4(oacc[i][0]*inv, oacc[i][1]*inv,
                                       oacc[i][2]*inv, oacc[i][3]*inv);
        *(float4*)(op+4) = make_float4(oacc[i][4]*inv, oacc[i][5]*inv,
                                       oacc[i][6]*inv, oacc[i][7]*inv);
    }
}

// ---------------------------------------------------------------------------
extern "C" void kernel_launch(void* const* d_in, const int* in_sizes, int n_in,
                              void* d_out, int out_size)
{
    const float* x  = (const float*)d_in[0];
    const float* fc = (const float*)d_in[1];
    const float* fs = (const float*)d_in[2];
    const float* wq = (const float*)d_in[3];
    const float* wk = (const float*)d_in[4];
    const float* wv = (const float*)d_in[5];
    const float* wo = (const float*)d_in[6];
    float* out = (float*)d_out;

    float *qp, *kp, *vp, *ap;
    cudaGetSymbolAddress((void**)&qp, g_q);
    cudaGetSymbolAddress((void**)&kp, g_k);
    cudaGetSymbolAddress((void**)&vp, g_v);
    cudaGetSymbolAddress((void**)&ap, g_attn);
    __nv_bfloat16 *xh,*xl,*ah,*al,*wqh,*wql,*wkh,*wkl,*wvh,*wvl,*woh,*wol;
    cudaGetSymbolAddress((void**)&xh, g_xh);  cudaGetSymbolAddress((void**)&xl, g_xl);
    cudaGetSymbolAddress((void**)&ah, g_ah);  cudaGetSymbolAddress((void**)&al, g_al);
    cudaGetSymbolAddress((void**)&wqh, g_wqh); cudaGetSymbolAddress((void**)&wql, g_wql);
    cudaGetSymbolAddress((void**)&wkh, g_wkh); cudaGetSymbolAddress((void**)&wkl, g_wkl);
    cudaGetSymbolAddress((void**)&wvh, g_wvh); cudaGetSymbolAddress((void**)&wvl, g_wvl);
    cudaGetSymbolAddress((void**)&woh, g_woh); cudaGetSymbolAddress((void**)&wol, g_wol);

    cudaFuncSetAttribute(flash_kernel,
                         cudaFuncAttributeMaxDynamicSharedMemorySize, FA_SMEM_BYTES);
    cudaFuncSetAttribute(gemm_bf16x3,
                         cudaFuncAttributeMaxDynamicSharedMemorySize, GEMM_SMEM_BYTES);

    const int n4_xd = T_ * D_ / 4;
    const int n4_w  = D_ * D_ / 4;
    const int n4_kv = KV_ * HD_ * D_ / 4;

    split_bf16<<<(n4_xd + 255)/256, 256>>>(x,  xh,  xl,  n4_xd);
    split_bf16<<<(n4_w  + 255)/256, 256>>>(wq, wqh, wql, n4_w);
    split_bf16<<<(n4_kv + 255)/256, 256>>>(wk, wkh, wkl, n4_kv);
    split_bf16<<<(n4_kv + 255)/256, 256>>>(wv, wvh, wvl, n4_kv);
    split_bf16<<<(n4_w  + 255)/256, 256>>>(wo, woh, wol, n4_w);

    dim3 blk(256);
    gemm_bf16x3<<<dim3(D_/128, T_/128), blk, GEMM_SMEM_BYTES>>>(
        xh, xl, wqh, wql, qp, T_, D_, D_);
    gemm_bf16x3<<<dim3((KV_*HD_)/128, T_/128), blk, GEMM_SMEM_BYTES>>>(
        xh, xl, wkh, wkl, kp, T_, KV_*HD_, D_);
    gemm_bf16x3<<<dim3((KV_*HD_)/128, T_/128), blk, GEMM_SMEM_BYTES>>>(
        xh, xl, wvh, wvl, vp, T_, KV_*HD_, D_);

    rope_kernel<<<(T_*H_*(HD_/2))/256,  256>>>(qp, fc, fs, H_);
    rope_kernel<<<(T_*KV_*(HD_/2))/256, 256>>>(kp, fc, fs, KV_);

    flash_kernel<<<dim3(S_/64, H_, B_), blk, FA_SMEM_BYTES>>>(qp, kp, vp, ap);

    split_bf16<<<(n4_xd + 255)/256, 256>>>(ap, ah, al, n4_xd);
    gemm_bf16x3<<<dim3(D_/128, T_/128), blk, GEMM_SMEM_BYTES>>>(
        ah, al, woh, wol, out, T_, D_, D_);
}

// round 4
// speedup vs baseline: 3.2621x; 1.6281x over previous
#include <cuda_runtime.h>
#include <cuda_bf16.h>
#include <math.h>
#include <cstdint>

#define B_ 2
#define S_ 2048
#define D_ 4096
#define H_ 32
#define KV_ 8
#define HD_ 128
#define T_ (B_*S_)
#define REP_ (H_/KV_)

// ---------------------------------------------------------------------------
// Scratch (device globals: allocation-free rule)
// ---------------------------------------------------------------------------
__device__ float g_q[T_ * D_];
__device__ float g_k[T_ * KV_ * HD_];
__device__ float g_v[T_ * KV_ * HD_];
__device__ float g_attn[T_ * D_];

__device__ __nv_bfloat16 g_xh[T_ * D_];
__device__ __nv_bfloat16 g_xl[T_ * D_];
__device__ __nv_bfloat16 g_ah[T_ * D_];
__device__ __nv_bfloat16 g_al[T_ * D_];
__device__ __nv_bfloat16 g_wqh[D_ * D_];
__device__ __nv_bfloat16 g_wql[D_ * D_];
__device__ __nv_bfloat16 g_wkh[KV_ * HD_ * D_];
__device__ __nv_bfloat16 g_wkl[KV_ * HD_ * D_];
__device__ __nv_bfloat16 g_wvh[KV_ * HD_ * D_];
__device__ __nv_bfloat16 g_wvl[KV_ * HD_ * D_];
__device__ __nv_bfloat16 g_woh[D_ * D_];
__device__ __nv_bfloat16 g_wol[D_ * D_];
// attention operand splits
__device__ __nv_bfloat16 g_qh[T_ * D_];
__device__ __nv_bfloat16 g_ql[T_ * D_];
__device__ __nv_bfloat16 g_kh[T_ * KV_ * HD_];
__device__ __nv_bfloat16 g_kl[T_ * KV_ * HD_];
__device__ __nv_bfloat16 g_vh[T_ * KV_ * HD_];
__device__ __nv_bfloat16 g_vl[T_ * KV_ * HD_];

// ---------------------------------------------------------------------------
// Helpers
// ---------------------------------------------------------------------------
__device__ __forceinline__ uint32_t smem_to_u32(const void* smem_ptr) {
    uint32_t addr;
    asm("{ .reg .u64 tmp; cvta.to.shared.u64 tmp, %1; cvt.u32.u64 %0, tmp; }"
        : "=r"(addr) : "l"(smem_ptr));
    return addr;
}
__device__ __forceinline__ void cp_async16(uint32_t saddr, const void* gaddr) {
    asm volatile("cp.async.cg.shared.global [%0], [%1], 16;"
                 :: "r"(saddr), "l"(gaddr));
}
#define CP_COMMIT() asm volatile("cp.async.commit_group;")
#define CP_WAIT(n)  asm volatile("cp.async.wait_group %0;" :: "n"(n))

__device__ __forceinline__ uint32_t lds32(uint32_t addr) {
    uint32_t v;
    asm("ld.shared.b32 %0, [%1];" : "=r"(v) : "r"(addr));
    return v;
}

#define MMA_BF16(d, a, b) \
    asm volatile("mma.sync.aligned.m16n8k16.row.col.f32.bf16.bf16.f32 " \
        "{%0,%1,%2,%3}, {%4,%5,%6,%7}, {%8,%9}, {%0,%1,%2,%3};" \
        : "+f"((d)[0]), "+f"((d)[1]), "+f"((d)[2]), "+f"((d)[3]) \
        : "r"((a)[0]), "r"((a)[1]), "r"((a)[2]), "r"((a)[3]), \
          "r"((b)[0]), "r"((b)[1]))

#define MMA4(d, a, bb0, bb1) \
    asm volatile("mma.sync.aligned.m16n8k16.row.col.f32.bf16.bf16.f32 " \
        "{%0,%1,%2,%3}, {%4,%5,%6,%7}, {%8,%9}, {%0,%1,%2,%3};" \
        : "+f"((d)[0]), "+f"((d)[1]), "+f"((d)[2]), "+f"((d)[3]) \
        : "r"((a)[0]), "r"((a)[1]), "r"((a)[2]), "r"((a)[3]), \
          "r"(bb0), "r"(bb1))

#define LDSM4(d0,d1,d2,d3,a) \
    asm volatile("ldmatrix.sync.aligned.m8n8.x4.shared.b16 {%0,%1,%2,%3}, [%4];" \
        : "=r"(d0), "=r"(d1), "=r"(d2), "=r"(d3) : "r"(a))
#define LDSM4T(d0,d1,d2,d3,a) \
    asm volatile("ldmatrix.sync.aligned.m8n8.x4.trans.shared.b16 {%0,%1,%2,%3}, [%4];" \
        : "=r"(d0), "=r"(d1), "=r"(d2), "=r"(d3) : "r"(a))

__device__ __forceinline__ uint32_t packbf(float lo, float hi) {
    uint32_t r;
    asm("cvt.rn.bf16x2.f32 %0, %1, %2;" : "=r"(r) : "f"(hi), "f"(lo));
    return r;
}
__device__ __forceinline__ float bf16_round(float x) {
    return __bfloat162float(__float2bfloat16(x));
}

// ---------------------------------------------------------------------------
// fp32 -> bf16 hi/lo split
// ---------------------------------------------------------------------------
__global__ void split_bf16(const float* __restrict__ X,
                           __nv_bfloat16* __restrict__ Hh,
                           __nv_bfloat16* __restrict__ Ll, int n4)
{
    int i = blockIdx.x * blockDim.x + threadIdx.x;
    if (i >= n4) return;
    float4 v = reinterpret_cast<const float4*>(X)[i];
    __nv_bfloat16 h0 = __float2bfloat16(v.x);
    __nv_bfloat16 h1 = __float2bfloat16(v.y);
    __nv_bfloat16 h2 = __float2bfloat16(v.z);
    __nv_bfloat16 h3 = __float2bfloat16(v.w);
    __nv_bfloat16 l0 = __float2bfloat16(v.x - __bfloat162float(h0));
    __nv_bfloat16 l1 = __float2bfloat16(v.y - __bfloat162float(h1));
    __nv_bfloat16 l2 = __float2bfloat16(v.z - __bfloat162float(h2));
    __nv_bfloat16 l3 = __float2bfloat16(v.w - __bfloat162float(h3));
    ushort4 hp, lp;
    hp.x = __bfloat16_as_ushort(h0); hp.y = __bfloat16_as_ushort(h1);
    hp.z = __bfloat16_as_ushort(h2); hp.w = __bfloat16_as_ushort(h3);
    lp.x = __bfloat16_as_ushort(l0); lp.y = __bfloat16_as_ushort(l1);
    lp.z = __bfloat16_as_ushort(l2); lp.w = __bfloat16_as_ushort(l3);
    reinterpret_cast<ushort4*>(Hh)[i] = hp;
    reinterpret_cast<ushort4*>(Ll)[i] = lp;
}

// ---------------------------------------------------------------------------
// bf16x3 GEMM via mma.sync (unchanged from R3 — ~500 TF/s)
// ---------------------------------------------------------------------------
#define GT_BYTES 16384
#define GSTAGE_BYTES (4 * GT_BYTES)
#define GEMM_SMEM_BYTES (2 * GSTAGE_BYTES)

__device__ __forceinline__ void gemm_stage_copy(
    uint32_t sbase, const __nv_bfloat16* a_h, const __nv_bfloat16* a_l,
    const __nv_bfloat16* b_h, const __nv_bfloat16* b_l,
    int K, int k0, int tid)
{
    const __nv_bfloat16* srcs[4] = {a_h, a_l, b_h, b_l};
    #pragma unroll
    for (int t = 0; t < 4; t++) {
        const __nv_bfloat16* src = srcs[t];
        #pragma unroll
        for (int p = 0; p < 4; p++) {
            int idx = p * 256 + tid;
            int row = idx >> 3;
            int ch  = idx & 7;
            const char* gp = (const char*)(src + (size_t)row * K + k0) + ch * 16;
            uint32_t soff = (uint32_t)(t * GT_BYTES + row * 128 +
                                       ((ch * 16) ^ ((row & 7) << 4)));
            cp_async16(sbase + soff, gp);
        }
    }
}

__global__ void __launch_bounds__(256, 1)
gemm_bf16x3(const __nv_bfloat16* __restrict__ Ah, const __nv_bfloat16* __restrict__ Al,
            const __nv_bfloat16* __restrict__ Bh, const __nv_bfloat16* __restrict__ Bl,
            float* __restrict__ C, int M, int N, int K)
{
    extern __shared__ __align__(1024) char smem[];
    const uint32_t sb0 = smem_to_u32(smem);
    const int tid  = threadIdx.x;
    const int wid  = tid >> 5;
    const int lane = tid & 31;
    const int bm = blockIdx.y * 128;
    const int bn = blockIdx.x * 128;
    const int warp_m = (wid >> 2) * 64;
    const int warp_n = (wid & 3) * 32;
    const int NC = K >> 6;

    const __nv_bfloat16* a_h = Ah + (size_t)bm * K;
    const __nv_bfloat16* a_l = Al + (size_t)bm * K;
    const __nv_bfloat16* b_h = Bh + (size_t)bn * K;
    const __nv_bfloat16* b_l = Bl + (size_t)bn * K;

    float acc[4][4][4];
    #pragma unroll
    for (int i = 0; i < 4; i++)
        #pragma unroll
        for (int j = 0; j < 4; j++)
            #pragma unroll
            for (int r = 0; r < 4; r++) acc[i][j][r] = 0.f;

    const int lg  = lane >> 2;
    const int lk4 = (lane & 3) * 4;

    gemm_stage_copy(sb0, a_h, a_l, b_h, b_l, K, 0, tid);
    CP_COMMIT();

    for (int c = 0; c < NC; c++) {
        if (c + 1 < NC) {
            gemm_stage_copy(sb0 + ((c + 1) & 1) * GSTAGE_BYTES,
                            a_h, a_l, b_h, b_l, K, (c + 1) << 6, tid);
            CP_COMMIT();
            CP_WAIT(1);
        } else {
            CP_WAIT(0);
        }
        __syncthreads();

        const uint32_t sb = sb0 + (c & 1) * GSTAGE_BYTES;

        #pragma unroll
        for (int ks = 0; ks < 4; ks++) {
            const int kb = ks * 32 + lk4;

            uint32_t ah[4][4], al[4][4], bh[4][2], bl[4][2];
            #pragma unroll
            for (int mt = 0; mt < 4; mt++) {
                int r0 = warp_m + mt * 16 + lg;
                int r1 = r0 + 8;
                uint32_t rb0 = r0 * 128, rx0 = (r0 & 7) << 4;
                uint32_t rb1 = r1 * 128, rx1 = (r1 & 7) << 4;
                ah[mt][0] = lds32(sb + rb0 + (kb ^ rx0));
                ah[mt][1] = lds32(sb + rb1 + (kb ^ rx1));
                ah[mt][2] = lds32(sb + rb0 + ((kb + 16) ^ rx0));
                ah[mt][3] = lds32(sb + rb1 + ((kb + 16) ^ rx1));
                al[mt][0] = lds32(sb + GT_BYTES + rb0 + (kb ^ rx0));
                al[mt][1] = lds32(sb + GT_BYTES + rb1 + (kb ^ rx1));
                al[mt][2] = lds32(sb + GT_BYTES + rb0 + ((kb + 16) ^ rx0));
                al[mt][3] = lds32(sb + GT_BYTES + rb1 + ((kb + 16) ^ rx1));
            }
            #pragma unroll
            for (int nt = 0; nt < 4; nt++) {
                int n = warp_n + nt * 8 + lg;
                uint32_t rb = n * 128, rx = (n & 7) << 4;
                bh[nt][0] = lds32(sb + 2*GT_BYTES + rb + (kb ^ rx));
                bh[nt][1] = lds32(sb + 2*GT_BYTES + rb + ((kb + 16) ^ rx));
                bl[nt][0] = lds32(sb + 3*GT_BYTES + rb + (kb ^ rx));
                bl[nt][1] = lds32(sb + 3*GT_BYTES + rb + ((kb + 16) ^ rx));
            }
            #pragma unroll
            for (int mt = 0; mt < 4; mt++)
                #pragma unroll
                for (int nt = 0; nt < 4; nt++) {
                    MMA_BF16(acc[mt][nt], ah[mt], bh[nt]);
                    MMA_BF16(acc[mt][nt], al[mt], bh[nt]);
                    MMA_BF16(acc[mt][nt], ah[mt], bl[nt]);
                }
        }
        __syncthreads();
    }

    #pragma unroll
    for (int mt = 0; mt < 4; mt++) {
        int row = bm + warp_m + mt * 16 + lg;
        #pragma unroll
        for (int nt = 0; nt < 4; nt++) {
            int col = bn + warp_n + nt * 8 + (lane & 3) * 2;
            *(float2*)(C + (size_t)row * N + col) =
                make_float2(acc[mt][nt][0], acc[mt][nt][1]);
            *(float2*)(C + (size_t)(row + 8) * N + col) =
                make_float2(acc[mt][nt][2], acc[mt][nt][3]);
        }
    }
}

// ---------------------------------------------------------------------------
// RoPE (interleaved pairs)
// ---------------------------------------------------------------------------
__global__ void rope_kernel(float* __restrict__ qk, const float* __restrict__ fc,
                            const float* __restrict__ fs, int heads)
{
    int idx = blockIdx.x * blockDim.x + threadIdx.x;
    int total = T_ * heads * (HD_/2);
    if (idx >= total) return;
    int i   = idx & 63;
    int rem = idx >> 6;
    int h   = rem % heads;
    int t   = rem / heads;
    int s   = t & (S_ - 1);
    float c  = fc[s*64 + i];
    float sn = fs[s*64 + i];
    size_t base = (size_t)t * heads * HD_ + h * HD_ + 2*i;
    float x0 = qk[base], x1 = qk[base+1];
    qk[base]   = x0 * c  - x1 * sn;
    qk[base+1] = x0 * sn + x1 * c;
}

// ---------------------------------------------------------------------------
// Tensorized flash attention (FA2-style), bf16x3 QK^T and PV, fp32 softmax.
// CTA: 128 q-rows x (head, batch). 8 warps x 16 rows. K-tile 64, double-buffer.
// Smem: Q(h,l) 64KB + 2 stages x (Kh,Kl,Vh,Vl) 64KB = 192KB.
// ---------------------------------------------------------------------------
#define FKT 16384                 // one K/V tensor tile: 64 rows x 256B
#define FSTAGE_BYTES (4 * FKT)    // 64KB
#define FQ_BYTES 32768            // one Q tensor tile: 128 rows x 256B
#define FA2_SMEM (2 * FQ_BYTES + 2 * FSTAGE_BYTES)   // 196608

__device__ __forceinline__ void fa_load_kv(
    uint32_t sbase,
    const __nv_bfloat16* kh, const __nv_bfloat16* kl,
    const __nv_bfloat16* vh, const __nv_bfloat16* vl,
    int tk0, int g, int tid)
{
    const __nv_bfloat16* srcs[4] = {kh, kl, vh, vl};
    #pragma unroll
    for (int tn = 0; tn < 4; tn++) {
        const __nv_bfloat16* src = srcs[tn] + (size_t)tk0 * (KV_*HD_) + g * HD_;
        #pragma unroll
        for (int it = 0; it < 4; it++) {
            int idx = it * 256 + tid;
            int key = idx >> 4;
            int gr  = idx & 15;
            uint32_t dst = sbase + tn * FKT + key * 256 +
                           (uint32_t)((gr * 16) ^ ((key & 7) << 4));
            cp_async16(dst, src + (size_t)key * (KV_*HD_) + gr * 8);
        }
    }
}

__global__ void __launch_bounds__(256, 1)
flash_mma(const __nv_bfloat16* __restrict__ Qh, const __nv_bfloat16* __restrict__ Ql,
          const __nv_bfloat16* __restrict__ Kh, const __nv_bfloat16* __restrict__ Kl,
          const __nv_bfloat16* __restrict__ Vh, const __nv_bfloat16* __restrict__ Vl,
          float* __restrict__ Og)
{
    extern __shared__ __align__(1024) char fsm[];
    const uint32_t sb = smem_to_u32(fsm);
    const int tid  = threadIdx.x;
    const int wid  = tid >> 5;
    const int lane = tid & 31;
    const int qt = (gridDim.x - 1) - blockIdx.x;   // heavy tiles first
    const int h  = blockIdx.y;
    const int b  = blockIdx.z;
    const int g  = h / REP_;
    const int q0 = qt * 128;
    const int t0 = b * S_ + q0;
    const int nt = 2 * qt + 2;
    const float scale = 0.08838834764831845f;

    // lane-derived constants
    const int l7    = lane & 7;
    const int lb8   = (lane >> 3) & 1;
    const int lhi16 = (lane >= 16) ? 16 : 0;
    const int qrow  = 16 * wid + l7 + lb8 * 8;       // Q frag row
    const uint32_t qswz = (uint32_t)(l7 << 4);
    const int krow_l = l7 + ((lane >= 16) ? 8 : 0);  // K frag key-in-16
    const int kgsel  = lb8 * 16;
    const uint32_t kswz = (uint32_t)(l7 << 4);
    const int vrow_l = l7 + lb8 * 8;                 // V frag key-in-16
    const int vgsel  = lhi16;
    const uint32_t vswz = (uint32_t)(l7 << 4);

    // prefetch KV tile 0 -> stage 0
    fa_load_kv(sb + 2*FQ_BYTES, Kh, Kl, Vh, Vl, b * S_, g, tid);
    CP_COMMIT();
    // stage Q (h and l)
    {
        const __nv_bfloat16* qsrc[2] = {Qh, Ql};
        #pragma unroll
        for (int tq = 0; tq < 2; tq++) {
            const __nv_bfloat16* src = qsrc[tq] + (size_t)t0 * D_ + h * HD_;
            #pragma unroll
            for (int it = 0; it < 8; it++) {
                int idx = it * 256 + tid;
                int row = idx >> 4;
                int gr  = idx & 15;
                uint32_t dst = sb + tq * FQ_BYTES + row * 256 +
                               (uint32_t)((gr * 16) ^ ((row & 7) << 4));
                cp_async16(dst, src + (size_t)row * D_ + gr * 8);
            }
        }
        CP_COMMIT();
    }

    float o[16][4];
    #pragma unroll
    for (int f = 0; f < 16; f++)
        #pragma unroll
        for (int r = 0; r < 4; r++) o[f][r] = 0.f;
    float m0 = -1e30f, m1 = -1e30f, l0 = 0.f, l1 = 0.f;

    const int r0g = q0 + 16 * wid + (lane >> 2);
    const int c0l = (lane & 3) * 2;

    for (int t = 0; t < nt; t++) {
        if (t + 1 < nt) {
            fa_load_kv(sb + 2*FQ_BYTES + ((t + 1) & 1) * FSTAGE_BYTES,
                       Kh, Kl, Vh, Vl, b * S_ + (t + 1) * 64, g, tid);
            CP_COMMIT();
            CP_WAIT(1);
        } else {
            CP_WAIT(0);
        }
        __syncthreads();

        const uint32_t kb  = sb + 2*FQ_BYTES + (t & 1) * FSTAGE_BYTES;
        const uint32_t vhb = kb + 2 * FKT;

        float s[8][4];
        #pragma unroll
        for (int j = 0; j < 8; j++)
            #pragma unroll
            for (int r = 0; r < 4; r++) s[j][r] = 0.f;

        // ---- S = Q K^T (bf16x3) ----
        #pragma unroll
        for (int kk = 0; kk < 8; kk++) {
            uint32_t qh[4], ql[4];
            uint32_t qa = sb + qrow * 256 + (uint32_t)(((kk * 32) + lhi16) ^ qswz);
            LDSM4(qh[0], qh[1], qh[2], qh[3], qa);
            LDSM4(ql[0], ql[1], ql[2], ql[3], qa + FQ_BYTES);
            #pragma unroll
            for (int np = 0; np < 4; np++) {
                uint32_t ka = kb + (np * 16 + krow_l) * 256 +
                              (uint32_t)(((kk * 32) + kgsel) ^ kswz);
                uint32_t b0, b1, b2, b3, c0, c1, c2, c3;
                LDSM4(b0, b1, b2, b3, ka);
                LDSM4(c0, c1, c2, c3, ka + FKT);
                MMA4(s[2*np],   qh, b0, b1);
                MMA4(s[2*np],   ql, b0, b1);
                MMA4(s[2*np],   qh, c0, c1);
                MMA4(s[2*np+1], qh, b2, b3);
                MMA4(s[2*np+1], ql, b2, b3);
                MMA4(s[2*np+1], qh, c2, c3);
            }
        }

        // ---- scale + causal mask ----
        const bool domask = (t >= 2 * qt);
        const int k0 = t * 64;
        #pragma unroll
        for (int j = 0; j < 8; j++) {
            s[j][0] *= scale; s[j][1] *= scale;
            s[j][2] *= scale; s[j][3] *= scale;
            if (domask) {
                int cg = k0 + 8 * j + c0l;
                if (cg     > r0g)     s[j][0] = -1e30f;
                if (cg + 1 > r0g)     s[j][1] = -1e30f;
                if (cg     > r0g + 8) s[j][2] = -1e30f;
                if (cg + 1 > r0g + 8) s[j][3] = -1e30f;
            }
        }

        // ---- online softmax ----
        float rm0 = -1e30f, rm1 = -1e30f;
        #pragma unroll
        for (int j = 0; j < 8; j++) {
            rm0 = fmaxf(rm0, fmaxf(s[j][0], s[j][1]));
            rm1 = fmaxf(rm1, fmaxf(s[j][2], s[j][3]));
        }
        rm0 = fmaxf(rm0, __shfl_xor_sync(0xffffffffu, rm0, 1));
        rm0 = fmaxf(rm0, __shfl_xor_sync(0xffffffffu, rm0, 2));
        rm1 = fmaxf(rm1, __shfl_xor_sync(0xffffffffu, rm1, 1));
        rm1 = fmaxf(rm1, __shfl_xor_sync(0xffffffffu, rm1, 2));
        float mn0 = fmaxf(m0, rm0), mn1 = fmaxf(m1, rm1);
        float a0 = __expf(m0 - mn0), a1 = __expf(m1 - mn1);
        m0 = mn0; m1 = mn1;
        float sum0 = 0.f, sum1 = 0.f;
        #pragma unroll
        for (int j = 0; j < 8; j++) {
            s[j][0] = __expf(s[j][0] - mn0);
            s[j][1] = __expf(s[j][1] - mn0);
            s[j][2] = __expf(s[j][2] - mn1);
            s[j][3] = __expf(s[j][3] - mn1);
            sum0 += s[j][0] + s[j][1];
            sum1 += s[j][2] + s[j][3];
        }
        sum0 += __shfl_xor_sync(0xffffffffu, sum0, 1);
        sum0 += __shfl_xor_sync(0xffffffffu, sum0, 2);
        sum1 += __shfl_xor_sync(0xffffffffu, sum1, 1);
        sum1 += __shfl_xor_sync(0xffffffffu, sum1, 2);
        l0 = l0 * a0 + sum0;
        l1 = l1 * a1 + sum1;
        #pragma unroll
        for (int f = 0; f < 16; f++) {
            o[f][0] *= a0; o[f][1] *= a0;
            o[f][2] *= a1; o[f][3] *= a1;
        }

        // ---- O += P V (bf16x3) ----
        #pragma unroll
        for (int kk = 0; kk < 4; kk++) {
            uint32_t ah[4], al[4];
            float p00 = s[2*kk][0],   p01 = s[2*kk][1];
            float p02 = s[2*kk][2],   p03 = s[2*kk][3];
            float p10 = s[2*kk+1][0], p11 = s[2*kk+1][1];
            float p12 = s[2*kk+1][2], p13 = s[2*kk+1][3];
            ah[0] = packbf(p00, p01);
            ah[1] = packbf(p02, p03);
            ah[2] = packbf(p10, p11);
            ah[3] = packbf(p12, p13);
            al[0] = packbf(p00 - bf16_round(p00), p01 - bf16_round(p01));
            al[1] = packbf(p02 - bf16_round(p02), p03 - bf16_round(p03));
            al[2] = packbf(p10 - bf16_round(p10), p11 - bf16_round(p11));
            al[3] = packbf(p12 - bf16_round(p12), p13 - bf16_round(p13));
            #pragma unroll
            for (int dgp = 0; dgp < 8; dgp++) {
                uint32_t va = vhb + (kk * 16 + vrow_l) * 256 +
                              (uint32_t)(((dgp * 32) + vgsel) ^ vswz);
                uint32_t b0, b1, b2, b3, c0, c1, c2, c3;
                LDSM4T(b0, b1, b2, b3, va);
                LDSM4T(c0, c1, c2, c3, va + FKT);
                MMA4(o[2*dgp],   ah, b0, b1);
                MMA4(o[2*dgp],   al, b0, b1);
                MMA4(o[2*dgp],   ah, c0, c1);
                MMA4(o[2*dgp+1], ah, b2, b3);
                MMA4(o[2*dgp+1], al, b2, b3);
                MMA4(o[2*dgp+1], ah, c2, c3);
            }
        }
        __syncthreads();
    }

    // ---- epilogue ----
    const float inv0 = 1.0f / l0;
    const float inv1 = 1.0f / l1;
    const int rowg = t0 + 16 * wid + (lane >> 2);
    #pragma unroll
    for (int dg = 0; dg < 16; dg++) {
        int col = h * HD_ + dg * 8 + (lane & 3) * 2;
        *(float2*)(Og + (size_t)rowg * D_ + col) =
            make_float2(o[dg][0] * inv0, o[dg][1] * inv0);
        *(float2*)(Og + (size_t)(rowg + 8) * D_ + col) =
            make_float2(o[dg][2] * inv1, o[dg][3] * inv1);
    }
}

// ---------------------------------------------------------------------------
extern "C" void kernel_launch(void* const* d_in, const int* in_sizes, int n_in,
                              void* d_out, int out_size)
{
    const float* x  = (const float*)d_in[0];
    const float* fc = (const float*)d_in[1];
    const float* fs = (const float*)d_in[2];
    const float* wq = (const float*)d_in[3];
    const float* wk = (const float*)d_in[4];
    const float* wv = (const float*)d_in[5];
    const float* wo = (const float*)d_in[6];
    float* out = (float*)d_out;

    float *qp, *kp, *vp, *ap;
    cudaGetSymbolAddress((void**)&qp, g_q);
    cudaGetSymbolAddress((void**)&kp, g_k);
    cudaGetSymbolAddress((void**)&vp, g_v);
    cudaGetSymbolAddress((void**)&ap, g_attn);
    __nv_bfloat16 *xh,*xl,*ah,*al,*wqh,*wql,*wkh,*wkl,*wvh,*wvl,*woh,*wol;
    __nv_bfloat16 *qh,*ql,*kh,*kl,*vh,*vl;
    cudaGetSymbolAddress((void**)&xh, g_xh);  cudaGetSymbolAddress((void**)&xl, g_xl);
    cudaGetSymbolAddress((void**)&ah, g_ah);  cudaGetSymbolAddress((void**)&al, g_al);
    cudaGetSymbolAddress((void**)&wqh, g_wqh); cudaGetSymbolAddress((void**)&wql, g_wql);
    cudaGetSymbolAddress((void**)&wkh, g_wkh); cudaGetSymbolAddress((void**)&wkl, g_wkl);
    cudaGetSymbolAddress((void**)&wvh, g_wvh); cudaGetSymbolAddress((void**)&wvl, g_wvl);
    cudaGetSymbolAddress((void**)&woh, g_woh); cudaGetSymbolAddress((void**)&wol, g_wol);
    cudaGetSymbolAddress((void**)&qh, g_qh);   cudaGetSymbolAddress((void**)&ql, g_ql);
    cudaGetSymbolAddress((void**)&kh, g_kh);   cudaGetSymbolAddress((void**)&kl, g_kl);
    cudaGetSymbolAddress((void**)&vh, g_vh);   cudaGetSymbolAddress((void**)&vl, g_vl);

    cudaFuncSetAttribute(gemm_bf16x3,
                         cudaFuncAttributeMaxDynamicSharedMemorySize, GEMM_SMEM_BYTES);
    cudaFuncSetAttribute(flash_mma,
                         cudaFuncAttributeMaxDynamicSharedMemorySize, FA2_SMEM);

    const int n4_xd = T_ * D_ / 4;
    const int n4_w  = D_ * D_ / 4;
    const int n4_kv = KV_ * HD_ * D_ / 4;
    const int n4_kvt = T_ * KV_ * HD_ / 4;

    split_bf16<<<(n4_xd + 255)/256, 256>>>(x,  xh,  xl,  n4_xd);
    split_bf16<<<(n4_w  + 255)/256, 256>>>(wq, wqh, wql, n4_w);
    split_bf16<<<(n4_kv + 255)/256, 256>>>(wk, wkh, wkl, n4_kv);
    split_bf16<<<(n4_kv + 255)/256, 256>>>(wv, wvh, wvl, n4_kv);
    split_bf16<<<(n4_w  + 255)/256, 256>>>(wo, woh, wol, n4_w);

    dim3 blk(256);
    gemm_bf16x3<<<dim3(D_/128, T_/128), blk, GEMM_SMEM_BYTES>>>(
        xh, xl, wqh, wql, qp, T_, D_, D_);
    gemm_bf16x3<<<dim3((KV_*HD_)/128, T_/128), blk, GEMM_SMEM_BYTES>>>(
        xh, xl, wkh, wkl, kp, T_, KV_*HD_, D_);
    gemm_bf16x3<<<dim3((KV_*HD_)/128, T_/128), blk, GEMM_SMEM_BYTES>>>(
        xh, xl, wvh, wvl, vp, T_, KV_*HD_, D_);

    rope_kernel<<<(T_*H_*(HD_/2))/256,  256>>>(qp, fc, fs, H_);
    rope_kernel<<<(T_*KV_*(HD_/2))/256, 256>>>(kp, fc, fs, KV_);

    // split rope'd Q/K and V for tensorized attention
    split_bf16<<<(n4_xd  + 255)/256, 256>>>(qp, qh, ql, n4_xd);
    split_bf16<<<(n4_kvt + 255)/256, 256>>>(kp, kh, kl, n4_kvt);
    split_bf16<<<(n4_kvt + 255)/256, 256>>>(vp, vh, vl, n4_kvt);

    flash_mma<<<dim3(S_/128, H_, B_), blk, FA2_SMEM>>>(qh, ql, kh, kl, vh, vl, ap);

    split_bf16<<<(n4_xd + 255)/256, 256>>>(ap, ah, al, n4_xd);
    gemm_bf16x3<<<dim3(D_/128, T_/128), blk, GEMM_SMEM_BYTES>>>(
        ah, al, woh, wol, out, T_, D_, D_);
}

// round 5
// speedup vs baseline: 3.9953x; 1.2247x over previous
#include <cuda_runtime.h>
#include <cuda_bf16.h>
#include <math.h>
#include <cstdint>

#define B_ 2
#define S_ 2048
#define D_ 4096
#define H_ 32
#define KV_ 8
#define HD_ 128
#define T_ (B_*S_)
#define REP_ (H_/KV_)

// ---------------------------------------------------------------------------
// Scratch (device globals: allocation-free rule)
// ---------------------------------------------------------------------------
__device__ float g_q[T_ * D_];
__device__ float g_k[T_ * KV_ * HD_];
__device__ float g_v[T_ * KV_ * HD_];
__device__ float g_attn[T_ * D_];

// tf32-rounded GEMM operands (fp32 storage, low mantissa bits zero)
__device__ float g_xt[T_ * D_];
__device__ float g_wqt[D_ * D_];
__device__ float g_wkt[KV_ * HD_ * D_];
__device__ float g_wvt[KV_ * HD_ * D_];
__device__ float g_wot[D_ * D_];
__device__ float g_at[T_ * D_];

// attention operand splits (bf16 hi/lo)
__device__ __nv_bfloat16 g_qh[T_ * D_];
__device__ __nv_bfloat16 g_ql[T_ * D_];
__device__ __nv_bfloat16 g_kh[T_ * KV_ * HD_];
__device__ __nv_bfloat16 g_kl[T_ * KV_ * HD_];
__device__ __nv_bfloat16 g_vh[T_ * KV_ * HD_];
__device__ __nv_bfloat16 g_vl[T_ * KV_ * HD_];

// ---------------------------------------------------------------------------
// Helpers
// ---------------------------------------------------------------------------
__device__ __forceinline__ uint32_t smem_to_u32(const void* smem_ptr) {
    uint32_t addr;
    asm("{ .reg .u64 tmp; cvta.to.shared.u64 tmp, %1; cvt.u32.u64 %0, tmp; }"
        : "=r"(addr) : "l"(smem_ptr));
    return addr;
}
__device__ __forceinline__ void cp_async16(uint32_t saddr, const void* gaddr) {
    asm volatile("cp.async.cg.shared.global [%0], [%1], 16;"
                 :: "r"(saddr), "l"(gaddr));
}
#define CP_COMMIT() asm volatile("cp.async.commit_group;")
#define CP_WAIT(n)  asm volatile("cp.async.wait_group %0;" :: "n"(n))

__device__ __forceinline__ uint32_t lds32(uint32_t addr) {
    uint32_t v;
    asm("ld.shared.b32 %0, [%1];" : "=r"(v) : "r"(addr));
    return v;
}

#define MMA_TF32(d, a, b) \
    asm volatile("mma.sync.aligned.m16n8k8.row.col.f32.tf32.tf32.f32 " \
        "{%0,%1,%2,%3}, {%4,%5,%6,%7}, {%8,%9}, {%0,%1,%2,%3};" \
        : "+f"((d)[0]), "+f"((d)[1]), "+f"((d)[2]), "+f"((d)[3]) \
        : "r"((a)[0]), "r"((a)[1]), "r"((a)[2]), "r"((a)[3]), \
          "r"((b)[0]), "r"((b)[1]))

#define MMA4(d, a, bb0, bb1) \
    asm volatile("mma.sync.aligned.m16n8k16.row.col.f32.bf16.bf16.f32 " \
        "{%0,%1,%2,%3}, {%4,%5,%6,%7}, {%8,%9}, {%0,%1,%2,%3};" \
        : "+f"((d)[0]), "+f"((d)[1]), "+f"((d)[2]), "+f"((d)[3]) \
        : "r"((a)[0]), "r"((a)[1]), "r"((a)[2]), "r"((a)[3]), \
          "r"(bb0), "r"(bb1))

#define LDSM4(d0,d1,d2,d3,a) \
    asm volatile("ldmatrix.sync.aligned.m8n8.x4.shared.b16 {%0,%1,%2,%3}, [%4];" \
        : "=r"(d0), "=r"(d1), "=r"(d2), "=r"(d3) : "r"(a))
#define LDSM4T(d0,d1,d2,d3,a) \
    asm volatile("ldmatrix.sync.aligned.m8n8.x4.trans.shared.b16 {%0,%1,%2,%3}, [%4];" \
        : "=r"(d0), "=r"(d1), "=r"(d2), "=r"(d3) : "r"(a))

__device__ __forceinline__ uint32_t packbf(float lo, float hi) {
    uint32_t r;
    asm("cvt.rn.bf16x2.f32 %0, %1, %2;" : "=r"(r) : "f"(hi), "f"(lo));
    return r;
}
__device__ __forceinline__ float bf16_round(float x) {
    return __bfloat162float(__float2bfloat16(x));
}
__device__ __forceinline__ uint32_t tf32_rna(float x) {
    uint32_t r;
    asm("cvt.rna.tf32.f32 %0, %1;" : "=r"(r) : "f"(x));
    return r;
}

// ---------------------------------------------------------------------------
// fp32 -> tf32 rounding (unbiased, so GEMM HW truncation is exact)
// ---------------------------------------------------------------------------
__global__ void round_tf32(const float* __restrict__ X, float* __restrict__ Y, int n4)
{
    int i = blockIdx.x * blockDim.x + threadIdx.x;
    if (i >= n4) return;
    float4 v = reinterpret_cast<const float4*>(X)[i];
    uint4 o;
    o.x = tf32_rna(v.x); o.y = tf32_rna(v.y);
    o.z = tf32_rna(v.z); o.w = tf32_rna(v.w);
    reinterpret_cast<uint4*>(Y)[i] = o;
}

// ---------------------------------------------------------------------------
// fp32 -> bf16 hi/lo split (for V)
// ---------------------------------------------------------------------------
__global__ void split_bf16(const float* __restrict__ X,
                           __nv_bfloat16* __restrict__ Hh,
                           __nv_bfloat16* __restrict__ Ll, int n4)
{
    int i = blockIdx.x * blockDim.x + threadIdx.x;
    if (i >= n4) return;
    float4 v = reinterpret_cast<const float4*>(X)[i];
    __nv_bfloat16 h0 = __float2bfloat16(v.x);
    __nv_bfloat16 h1 = __float2bfloat16(v.y);
    __nv_bfloat16 h2 = __float2bfloat16(v.z);
    __nv_bfloat16 h3 = __float2bfloat16(v.w);
    __nv_bfloat16 l0 = __float2bfloat16(v.x - __bfloat162float(h0));
    __nv_bfloat16 l1 = __float2bfloat16(v.y - __bfloat162float(h1));
    __nv_bfloat16 l2 = __float2bfloat16(v.z - __bfloat162float(h2));
    __nv_bfloat16 l3 = __float2bfloat16(v.w - __bfloat162float(h3));
    ushort4 hp, lp;
    hp.x = __bfloat16_as_ushort(h0); hp.y = __bfloat16_as_ushort(h1);
    hp.z = __bfloat16_as_ushort(h2); hp.w = __bfloat16_as_ushort(h3);
    lp.x = __bfloat16_as_ushort(l0); lp.y = __bfloat16_as_ushort(l1);
    lp.z = __bfloat16_as_ushort(l2); lp.w = __bfloat16_as_ushort(l3);
    reinterpret_cast<ushort4*>(Hh)[i] = hp;
    reinterpret_cast<ushort4*>(Ll)[i] = lp;
}

// ---------------------------------------------------------------------------
// Fused RoPE + bf16 hi/lo split (Q and K): read pre-rope fp32, write hi/lo.
// Thread = 4 contiguous elements (2 rope pairs).
// ---------------------------------------------------------------------------
__global__ void rope_split(const float* __restrict__ src,
                           __nv_bfloat16* __restrict__ Hh,
                           __nv_bfloat16* __restrict__ Ll,
                           const float* __restrict__ fc,
                           const float* __restrict__ fs, int heads)
{
    int idx = blockIdx.x * blockDim.x + threadIdx.x;
    int total = T_ * heads * (HD_/4);
    if (idx >= total) return;
    int i32 = idx & 31;          // 4-elem group within head dim
    int rem = idx >> 5;
    int h   = rem % heads;
    int t   = rem / heads;
    int s   = t & (S_ - 1);
    int p0  = 2 * i32;
    float c0 = fc[s*64 + p0],     s0 = fs[s*64 + p0];
    float c1 = fc[s*64 + p0 + 1], s1 = fs[s*64 + p0 + 1];
    size_t base = (size_t)t * heads * HD_ + h * HD_ + 4*i32;
    float4 v = *reinterpret_cast<const float4*>(src + base);
    float r0 = v.x * c0 - v.y * s0;
    float r1 = v.x * s0 + v.y * c0;
    float r2 = v.z * c1 - v.w * s1;
    float r3 = v.z * s1 + v.w * c1;
    __nv_bfloat16 h0 = __float2bfloat16(r0), h1 = __float2bfloat16(r1);
    __nv_bfloat16 h2 = __float2bfloat16(r2), h3 = __float2bfloat16(r3);
    __nv_bfloat16 l0 = __float2bfloat16(r0 - __bfloat162float(h0));
    __nv_bfloat16 l1 = __float2bfloat16(r1 - __bfloat162float(h1));
    __nv_bfloat16 l2 = __float2bfloat16(r2 - __bfloat162float(h2));
    __nv_bfloat16 l3 = __float2bfloat16(r3 - __bfloat162float(h3));
    ushort4 hp, lp;
    hp.x = __bfloat16_as_ushort(h0); hp.y = __bfloat16_as_ushort(h1);
    hp.z = __bfloat16_as_ushort(h2); hp.w = __bfloat16_as_ushort(h3);
    lp.x = __bfloat16_as_ushort(l0); lp.y = __bfloat16_as_ushort(l1);
    lp.z = __bfloat16_as_ushort(l2); lp.w = __bfloat16_as_ushort(l3);
    *reinterpret_cast<ushort4*>(Hh + base) = hp;
    *reinterpret_cast<ushort4*>(Ll + base) = lp;
}

// ---------------------------------------------------------------------------
// tf32 single-pass GEMM: C[M,N] = A[M,K] @ W[N,K]^T, fp32 accumulate.
// CTA 128x128, BK=64 floats (256B rows), 3-stage cp.async, 1 sync/chunk.
// 8 warps (2x4), warp tile 64x32. mma m16n8k8.tf32 (operands pre-rounded).
// ---------------------------------------------------------------------------
#define AT_BYTES (128 * 256)          // 32KB per tensor tile
#define STG_BYTES (2 * AT_BYTES)      // A + B = 64KB per stage
#define G3_SMEM (3 * STG_BYTES)       // 192KB

__device__ __forceinline__ void gemm_stage_copy(
    uint32_t sbase, const float* __restrict__ A128, const float* __restrict__ B128,
    int K, int k0, int tid)
{
    #pragma unroll
    for (int t = 0; t < 2; t++) {
        const float* src = t ? B128 : A128;
        #pragma unroll
        for (int it = 0; it < 8; it++) {
            int idx = it * 256 + tid;       // 0..2047
            int row = idx >> 4;
            int gr  = idx & 15;
            uint32_t dst = sbase + t * AT_BYTES + row * 256 +
                           (uint32_t)((gr * 16) ^ ((row & 7) << 4));
            cp_async16(dst, src + (size_t)row * K + k0 + gr * 4);
        }
    }
}

__global__ void __launch_bounds__(256, 1)
gemm_tf32(const float* __restrict__ A, const float* __restrict__ Bw,
          float* __restrict__ C, int M, int N, int K)
{
    extern __shared__ __align__(1024) char smem[];
    const uint32_t sb0 = smem_to_u32(smem);
    const int tid  = threadIdx.x;
    const int wid  = tid >> 5;
    const int lane = tid & 31;
    const int bm = blockIdx.y * 128;
    const int bn = blockIdx.x * 128;
    const int warp_m = (wid >> 2) * 64;
    const int warp_n = (wid & 3) * 32;
    const int NC = K >> 6;

    const float* A128 = A  + (size_t)bm * K;
    const float* B128 = Bw + (size_t)bn * K;

    float acc[4][4][4];
    #pragma unroll
    for (int i = 0; i < 4; i++)
        #pragma unroll
        for (int j = 0; j < 4; j++)
            #pragma unroll
            for (int r = 0; r < 4; r++) acc[i][j][r] = 0.f;

    const int grp  = lane >> 2;       // 0..7
    const int krem = (lane & 3) * 4;  // byte offset within 16B

    gemm_stage_copy(sb0, A128, B128, K, 0, tid);
    CP_COMMIT();
    gemm_stage_copy(sb0 + STG_BYTES, A128, B128, K, 64, tid);
    CP_COMMIT();

    int stage = 0;
    for (int c = 0; c < NC; c++) {
        if (c + 1 < NC) { CP_WAIT(1); } else { CP_WAIT(0); }
        __syncthreads();
        if (c + 2 < NC) {
            int ns = stage + 2; if (ns >= 3) ns -= 3;
            gemm_stage_copy(sb0 + ns * STG_BYTES, A128, B128, K, (c + 2) << 6, tid);
            CP_COMMIT();
        }
        const uint32_t sb = sb0 + stage * STG_BYTES;
        if (++stage == 3) stage = 0;

        #pragma unroll
        for (int ks = 0; ks < 8; ks++) {
            const uint32_t kbyte = ks * 32;

            uint32_t a[4][4], bfr[4][2];
            #pragma unroll
            for (int mt = 0; mt < 4; mt++) {
                int row = warp_m + mt * 16 + grp;
                uint32_t base  = sb + row * 256;
                uint32_t swz   = (uint32_t)((row & 7) << 4);
                a[mt][0] = lds32(base        + ((kbyte + krem)      ^ swz));
                a[mt][1] = lds32(base + 2048 + ((kbyte + krem)      ^ swz));
                a[mt][2] = lds32(base        + ((kbyte + 16 + krem) ^ swz));
                a[mt][3] = lds32(base + 2048 + ((kbyte + 16 + krem) ^ swz));
            }
            #pragma unroll
            for (int nt = 0; nt < 4; nt++) {
                int n = warp_n + nt * 8 + grp;
                uint32_t base = sb + AT_BYTES + n * 256;
                uint32_t swz  = (uint32_t)((n & 7) << 4);
                bfr[nt][0] = lds32(base + ((kbyte + krem)      ^ swz));
                bfr[nt][1] = lds32(base + ((kbyte + 16 + krem) ^ swz));
            }
            #pragma unroll
            for (int mt = 0; mt < 4; mt++)
                #pragma unroll
                for (int nt = 0; nt < 4; nt++)
                    MMA_TF32(acc[mt][nt], a[mt], bfr[nt]);
        }
    }

    #pragma unroll
    for (int mt = 0; mt < 4; mt++) {
        int row = bm + warp_m + mt * 16 + grp;
        #pragma unroll
        for (int nt = 0; nt < 4; nt++) {
            int col = bn + warp_n + nt * 8 + (lane & 3) * 2;
            *(float2*)(C + (size_t)row * N + col) =
                make_float2(acc[mt][nt][0], acc[mt][nt][1]);
            *(float2*)(C + (size_t)(row + 8) * N + col) =
                make_float2(acc[mt][nt][2], acc[mt][nt][3]);
        }
    }
}

// ---------------------------------------------------------------------------
// Tensorized flash attention (unchanged from R4 — bf16x3, known correct)
// ---------------------------------------------------------------------------
#define FKT 16384
#define FSTAGE_BYTES (4 * FKT)
#define FQ_BYTES 32768
#define FA2_SMEM (2 * FQ_BYTES + 2 * FSTAGE_BYTES)

__device__ __forceinline__ void fa_load_kv(
    uint32_t sbase,
    const __nv_bfloat16* kh, const __nv_bfloat16* kl,
    const __nv_bfloat16* vh, const __nv_bfloat16* vl,
    int tk0, int g, int tid)
{
    const __nv_bfloat16* srcs[4] = {kh, kl, vh, vl};
    #pragma unroll
    for (int tn = 0; tn < 4; tn++) {
        const __nv_bfloat16* src = srcs[tn] + (size_t)tk0 * (KV_*HD_) + g * HD_;
        #pragma unroll
        for (int it = 0; it < 4; it++) {
            int idx = it * 256 + tid;
            int key = idx >> 4;
            int gr  = idx & 15;
            uint32_t dst = sbase + tn * FKT + key * 256 +
                           (uint32_t)((gr * 16) ^ ((key & 7) << 4));
            cp_async16(dst, src + (size_t)key * (KV_*HD_) + gr * 8);
        }
    }
}

__global__ void __launch_bounds__(256, 1)
flash_mma(const __nv_bfloat16* __restrict__ Qh, const __nv_bfloat16* __restrict__ Ql,
          const __nv_bfloat16* __restrict__ Kh, const __nv_bfloat16* __restrict__ Kl,
          const __nv_bfloat16* __restrict__ Vh, const __nv_bfloat16* __restrict__ Vl,
          float* __restrict__ Og)
{
    extern __shared__ __align__(1024) char fsm[];
    const uint32_t sb = smem_to_u32(fsm);
    const int tid  = threadIdx.x;
    const int wid  = tid >> 5;
    const int lane = tid & 31;
    const int qt = (gridDim.x - 1) - blockIdx.x;
    const int h  = blockIdx.y;
    const int b  = blockIdx.z;
    const int g  = h / REP_;
    const int q0 = qt * 128;
    const int t0 = b * S_ + q0;
    const int nt = 2 * qt + 2;
    const float scale = 0.08838834764831845f;

    const int l7    = lane & 7;
    const int lb8   = (lane >> 3) & 1;
    const int lhi16 = (lane >= 16) ? 16 : 0;
    const int qrow  = 16 * wid + l7 + lb8 * 8;
    const uint32_t qswz = (uint32_t)(l7 << 4);
    const int krow_l = l7 + ((lane >= 16) ? 8 : 0);
    const int kgsel  = lb8 * 16;
    const uint32_t kswz = (uint32_t)(l7 << 4);
    const int vrow_l = l7 + lb8 * 8;
    const int vgsel  = lhi16;
    const uint32_t vswz = (uint32_t)(l7 << 4);

    fa_load_kv(sb + 2*FQ_BYTES, Kh, Kl, Vh, Vl, b * S_, g, tid);
    CP_COMMIT();
    {
        const __nv_bfloat16* qsrc[2] = {Qh, Ql};
        #pragma unroll
        for (int tq = 0; tq < 2; tq++) {
            const __nv_bfloat16* src = qsrc[tq] + (size_t)t0 * D_ + h * HD_;
            #pragma unroll
            for (int it = 0; it < 8; it++) {
                int idx = it * 256 + tid;
                int row = idx >> 4;
                int gr  = idx & 15;
                uint32_t dst = sb + tq * FQ_BYTES + row * 256 +
                               (uint32_t)((gr * 16) ^ ((row & 7) << 4));
                cp_async16(dst, src + (size_t)row * D_ + gr * 8);
            }
        }
        CP_COMMIT();
    }

    float o[16][4];
    #pragma unroll
    for (int f = 0; f < 16; f++)
        #pragma unroll
        for (int r = 0; r < 4; r++) o[f][r] = 0.f;
    float m0 = -1e30f, m1 = -1e30f, l0 = 0.f, l1 = 0.f;

    const int r0g = q0 + 16 * wid + (lane >> 2);
    const int c0l = (lane & 3) * 2;

    for (int t = 0; t < nt; t++) {
        if (t + 1 < nt) {
            fa_load_kv(sb + 2*FQ_BYTES + ((t + 1) & 1) * FSTAGE_BYTES,
                       Kh, Kl, Vh, Vl, b * S_ + (t + 1) * 64, g, tid);
            CP_COMMIT();
            CP_WAIT(1);
        } else {
            CP_WAIT(0);
        }
        __syncthreads();

        const uint32_t kb  = sb + 2*FQ_BYTES + (t & 1) * FSTAGE_BYTES;
        const uint32_t vhb = kb + 2 * FKT;

        float s[8][4];
        #pragma unroll
        for (int j = 0; j < 8; j++)
            #pragma unroll
            for (int r = 0; r < 4; r++) s[j][r] = 0.f;

        #pragma unroll
        for (int kk = 0; kk < 8; kk++) {
            uint32_t qh[4], ql[4];
            uint32_t qa = sb + qrow * 256 + (uint32_t)(((kk * 32) + lhi16) ^ qswz);
            LDSM4(qh[0], qh[1], qh[2], qh[3], qa);
            LDSM4(ql[0], ql[1], ql[2], ql[3], qa + FQ_BYTES);
            #pragma unroll
            for (int np = 0; np < 4; np++) {
                uint32_t ka = kb + (np * 16 + krow_l) * 256 +
                              (uint32_t)(((kk * 32) + kgsel) ^ kswz);
                uint32_t b0, b1, b2, b3, c0, c1, c2, c3;
                LDSM4(b0, b1, b2, b3, ka);
                LDSM4(c0, c1, c2, c3, ka + FKT);
                MMA4(s[2*np],   qh, b0, b1);
                MMA4(s[2*np],   ql, b0, b1);
                MMA4(s[2*np],   qh, c0, c1);
                MMA4(s[2*np+1], qh, b2, b3);
                MMA4(s[2*np+1], ql, b2, b3);
                MMA4(s[2*np+1], qh, c2, c3);
            }
        }

        const bool domask = (t >= 2 * qt);
        const int k0 = t * 64;
        #pragma unroll
        for (int j = 0; j < 8; j++) {
            s[j][0] *= scale; s[j][1] *= scale;
            s[j][2] *= scale; s[j][3] *= scale;
            if (domask) {
                int cg = k0 + 8 * j + c0l;
                if (cg     > r0g)     s[j][0] = -1e30f;
                if (cg + 1 > r0g)     s[j][1] = -1e30f;
                if (cg     > r0g + 8) s[j][2] = -1e30f;
                if (cg + 1 > r0g + 8) s[j][3] = -1e30f;
            }
        }

        float rm0 = -1e30f, rm1 = -1e30f;
        #pragma unroll
        for (int j = 0; j < 8; j++) {
            rm0 = fmaxf(rm0, fmaxf(s[j][0], s[j][1]));
            rm1 = fmaxf(rm1, fmaxf(s[j][2], s[j][3]));
        }
        rm0 = fmaxf(rm0, __shfl_xor_sync(0xffffffffu, rm0, 1));
        rm0 = fmaxf(rm0, __shfl_xor_sync(0xffffffffu, rm0, 2));
        rm1 = fmaxf(rm1, __shfl_xor_sync(0xffffffffu, rm1, 1));
        rm1 = fmaxf(rm1, __shfl_xor_sync(0xffffffffu, rm1, 2));
        float mn0 = fmaxf(m0, rm0), mn1 = fmaxf(m1, rm1);
        float a0 = __expf(m0 - mn0), a1 = __expf(m1 - mn1);
        m0 = mn0; m1 = mn1;
        float sum0 = 0.f, sum1 = 0.f;
        #pragma unroll
        for (int j = 0; j < 8; j++) {
            s[j][0] = __expf(s[j][0] - mn0);
            s[j][1] = __expf(s[j][1] - mn0);
            s[j][2] = __expf(s[j][2] - mn1);
            s[j][3] = __expf(s[j][3] - mn1);
            sum0 += s[j][0] + s[j][1];
            sum1 += s[j][2] + s[j][3];
        }
        sum0 += __shfl_xor_sync(0xffffffffu, sum0, 1);
        sum0 += __shfl_xor_sync(0xffffffffu, sum0, 2);
        sum1 += __shfl_xor_sync(0xffffffffu, sum1, 1);
        sum1 += __shfl_xor_sync(0xffffffffu, sum1, 2);
        l0 = l0 * a0 + sum0;
        l1 = l1 * a1 + sum1;
        #pragma unroll
        for (int f = 0; f < 16; f++) {
            o[f][0] *= a0; o[f][1] *= a0;
            o[f][2] *= a1; o[f][3] *= a1;
        }

        #pragma unroll
        for (int kk = 0; kk < 4; kk++) {
            uint32_t ah[4], al[4];
            float p00 = s[2*kk][0],   p01 = s[2*kk][1];
            float p02 = s[2*kk][2],   p03 = s[2*kk][3];
            float p10 = s[2*kk+1][0], p11 = s[2*kk+1][1];
            float p12 = s[2*kk+1][2], p13 = s[2*kk+1][3];
            ah[0] = packbf(p00, p01);
            ah[1] = packbf(p02, p03);
            ah[2] = packbf(p10, p11);
            ah[3] = packbf(p12, p13);
            al[0] = packbf(p00 - bf16_round(p00), p01 - bf16_round(p01));
            al[1] = packbf(p02 - bf16_round(p02), p03 - bf16_round(p03));
            al[2] = packbf(p10 - bf16_round(p10), p11 - bf16_round(p11));
            al[3] = packbf(p12 - bf16_round(p12), p13 - bf16_round(p13));
            #pragma unroll
            for (int dgp = 0; dgp < 8; dgp++) {
                uint32_t va = vhb + (kk * 16 + vrow_l) * 256 +
                              (uint32_t)(((dgp * 32) + vgsel) ^ vswz);
                uint32_t b0, b1, b2, b3, c0, c1, c2, c3;
                LDSM4T(b0, b1, b2, b3, va);
                LDSM4T(c0, c1, c2, c3, va + FKT);
                MMA4(o[2*dgp],   ah, b0, b1);
                MMA4(o[2*dgp],   al, b0, b1);
                MMA4(o[2*dgp],   ah, c0, c1);
                MMA4(o[2*dgp+1], ah, b2, b3);
                MMA4(o[2*dgp+1], al, b2, b3);
                MMA4(o[2*dgp+1], ah, c2, c3);
            }
        }
        __syncthreads();
    }

    const float inv0 = 1.0f / l0;
    const float inv1 = 1.0f / l1;
    const int rowg = t0 + 16 * wid + (lane >> 2);
    #pragma unroll
    for (int dg = 0; dg < 16; dg++) {
        int col = h * HD_ + dg * 8 + (lane & 3) * 2;
        *(float2*)(Og + (size_t)rowg * D_ + col) =
            make_float2(o[dg][0] * inv0, o[dg][1] * inv0);
        *(float2*)(Og + (size_t)(rowg + 8) * D_ + col) =
            make_float2(o[dg][2] * inv1, o[dg][3] * inv1);
    }
}

// ---------------------------------------------------------------------------
extern "C" void kernel_launch(void* const* d_in, const int* in_sizes, int n_in,
                              void* d_out, int out_size)
{
    const float* x  = (const float*)d_in[0];
    const float* fc = (const float*)d_in[1];
    const float* fs = (const float*)d_in[2];
    const float* wq = (const float*)d_in[3];
    const float* wk = (const float*)d_in[4];
    const float* wv = (const float*)d_in[5];
    const float* wo = (const float*)d_in[6];
    float* out = (float*)d_out;

    float *qp, *kp, *vp, *ap;
    float *xt, *wqt, *wkt, *wvt, *wot, *at;
    cudaGetSymbolAddress((void**)&qp, g_q);
    cudaGetSymbolAddress((void**)&kp, g_k);
    cudaGetSymbolAddress((void**)&vp, g_v);
    cudaGetSymbolAddress((void**)&ap, g_attn);
    cudaGetSymbolAddress((void**)&xt, g_xt);
    cudaGetSymbolAddress((void**)&wqt, g_wqt);
    cudaGetSymbolAddress((void**)&wkt, g_wkt);
    cudaGetSymbolAddress((void**)&wvt, g_wvt);
    cudaGetSymbolAddress((void**)&wot, g_wot);
    cudaGetSymbolAddress((void**)&at, g_at);
    __nv_bfloat16 *qh,*ql,*kh,*kl,*vh,*vl;
    cudaGetSymbolAddress((void**)&qh, g_qh);   cudaGetSymbolAddress((void**)&ql, g_ql);
    cudaGetSymbolAddress((void**)&kh, g_kh);   cudaGetSymbolAddress((void**)&kl, g_kl);
    cudaGetSymbolAddress((void**)&vh, g_vh);   cudaGetSymbolAddress((void**)&vl, g_vl);

    cudaFuncSetAttribute(gemm_tf32,
                         cudaFuncAttributeMaxDynamicSharedMemorySize, G3_SMEM);
    cudaFuncSetAttribute(flash_mma,
                         cudaFuncAttributeMaxDynamicSharedMemorySize, FA2_SMEM);

    const int n4_xd = T_ * D_ / 4;
    const int n4_w  = D_ * D_ / 4;
    const int n4_kv = KV_ * HD_ * D_ / 4;
    const int n4_kvt = T_ * KV_ * HD_ / 4;

    round_tf32<<<(n4_xd + 255)/256, 256>>>(x,  xt,  n4_xd);
    round_tf32<<<(n4_w  + 255)/256, 256>>>(wq, wqt, n4_w);
    round_tf32<<<(n4_kv + 255)/256, 256>>>(wk, wkt, n4_kv);
    round_tf32<<<(n4_kv + 255)/256, 256>>>(wv, wvt, n4_kv);
    round_tf32<<<(n4_w  + 255)/256, 256>>>(wo, wot, n4_w);

    dim3 blk(256);
    gemm_tf32<<<dim3(D_/128, T_/128), blk, G3_SMEM>>>(xt, wqt, qp, T_, D_, D_);
    gemm_tf32<<<dim3((KV_*HD_)/128, T_/128), blk, G3_SMEM>>>(xt, wkt, kp, T_, KV_*HD_, D_);
    gemm_tf32<<<dim3((KV_*HD_)/128, T_/128), blk, G3_SMEM>>>(xt, wvt, vp, T_, KV_*HD_, D_);

    // fused RoPE + split for Q/K; plain split for V
    rope_split<<<(T_*H_*(HD_/4))/256,  256>>>(qp, qh, ql, fc, fs, H_);
    rope_split<<<(T_*KV_*(HD_/4))/256, 256>>>(kp, kh, kl, fc, fs, KV_);
    split_bf16<<<(n4_kvt + 255)/256, 256>>>(vp, vh, vl, n4_kvt);

    flash_mma<<<dim3(S_/128, H_, B_), blk, FA2_SMEM>>>(qh, ql, kh, kl, vh, vl, ap);

    round_tf32<<<(n4_xd + 255)/256, 256>>>(ap, at, n4_xd);
    gemm_tf32<<<dim3(D_/128, T_/128), blk, G3_SMEM>>>(at, wot, out, T_, D_, D_);
}